// round 14
// baseline (speedup 1.0000x reference)
#include <cuda_runtime.h>
#include <cuda_fp16.h>
#include <cuda_bf16.h>
#include <math_constants.h>
#include <cstdint>

#define ENC_DIM 256
#define INT_DIM 256
#define MT 64                   // rows per CTA (M)
#define NT 256                  // hidden per CTA (N)
#define KC 32                   // k per chunk
#define NCHUNK (ENC_DIM / KC)   // 8
#define NKS (KC / 16)           // 2 k16 steps per chunk
#define P 20                    // smem pitch in u32 words (16 used + 4 pad)
#define ASZ (MT * P)            // 1280 words (one A chunk buffer)
#define BSZ (NT * P)            // 5120 words (one B stage)
#define BSTG 3                  // B pipeline stages
#define DYN_BYTES ((NCHUNK * ASZ + BSTG * BSZ) * 4)   // 102400 -> 2 CTAs/SM
#define NTHR 256
#define MAXCPB 32               // chunks per batch (T/MT)

// Scratch (allocation-free rule: __device__ globals)
__device__ float  g_dp[64 * INT_DIM];          // dec_proj [B, I]
__device__ float  g_scores[64 * 2048];         // scores   [B, T]
__device__ __half g_w1h[INT_DIM * ENC_DIM];    // w1 as fp16, [n][k]
__device__ float  g_pm[2048];                  // per-CTA local max
__device__ float  g_pz[2048];                  // per-CTA local exp-sum
__device__ float  g_pctx[2048 * ENC_DIM];      // per-CTA partial context
__device__ float  g_mz[128];                   // per-batch {m, Z}

// ---------------------------------------------------------------------------
// helpers
// ---------------------------------------------------------------------------
__device__ __forceinline__ float tanha(float x) {
    float y;
    asm("tanh.approx.f32 %0, %1;" : "=f"(y) : "f"(x));
    return y;
}
// .ca: allow L1 caching -- B (w1h, 128KB) is re-read by every CTA on the SM,
// L1 residency cuts the contended L2 share out of the staging path.
__device__ __forceinline__ void cp16ca(unsigned dst_s, const void* src) {
    asm volatile("cp.async.ca.shared.global [%0], [%1], 16;"
                 :: "r"(dst_s), "l"(src) : "memory");
}
__device__ __forceinline__ void cp_commit() {
    asm volatile("cp.async.commit_group;" ::: "memory");
}
template <int N>
__device__ __forceinline__ void cp_wait() {
    asm volatile("cp.async.wait_group %0;" :: "n"(N) : "memory");
}
__device__ __forceinline__ unsigned s2u(const void* p) {
    return (unsigned)__cvta_generic_to_shared(p);
}
__device__ __forceinline__ void ldsm4(unsigned r[4], unsigned addr) {
    asm volatile("ldmatrix.sync.aligned.m8n8.x4.shared.b16 "
                 "{%0,%1,%2,%3}, [%4];"
                 : "=r"(r[0]), "=r"(r[1]), "=r"(r[2]), "=r"(r[3])
                 : "r"(addr));
}
__device__ __forceinline__ void mma_f16(float d[4], const unsigned a[4],
                                        unsigned b0, unsigned b1) {
    asm volatile(
        "mma.sync.aligned.m16n8k16.row.col.f32.f16.f16.f32 "
        "{%0,%1,%2,%3}, {%4,%5,%6,%7}, {%8,%9}, {%0,%1,%2,%3};"
        : "+f"(d[0]), "+f"(d[1]), "+f"(d[2]), "+f"(d[3])
        : "r"(a[0]), "r"(a[1]), "r"(a[2]), "r"(a[3]), "r"(b0), "r"(b1));
}

// ---------------------------------------------------------------------------
// K0: fused prep (dec_proj + w1 -> fp16). grid = 64 x 256.
// ---------------------------------------------------------------------------
__global__ void prep_kernel(const float* __restrict__ dec,
                            const float* __restrict__ w2,
                            const float* __restrict__ w1,
                            __half* __restrict__ w1h,
                            float* __restrict__ dp) {
    __shared__ float ds[ENC_DIM];
    const int b = blockIdx.x;
    const int tid = threadIdx.x;
    const int lane = tid & 31, wid = tid >> 5;

    ds[tid] = dec[b * ENC_DIM + tid];

    {
        const int base = b * 1024 + tid * 4;
        float4 wv = *reinterpret_cast<const float4*>(w1 + base);
        __half2 p0 = __floats2half2_rn(wv.x, wv.y);
        __half2 p1 = __floats2half2_rn(wv.z, wv.w);
        uint2 pk = make_uint2(*reinterpret_cast<uint32_t*>(&p0),
                              *reinterpret_cast<uint32_t*>(&p1));
        *reinterpret_cast<uint2*>(w1h + base) = pk;
    }
    __syncthreads();

#pragma unroll 4
    for (int ii = 0; ii < 32; ++ii) {
        const int i = wid * 32 + ii;
        float acc = 0.f;
#pragma unroll
        for (int kk = 0; kk < 8; ++kk) {
            const int k = kk * 32 + lane;
            acc = fmaf(__ldg(w2 + i * ENC_DIM + k), ds[k], acc);
        }
#pragma unroll
        for (int o = 16; o; o >>= 1) acc += __shfl_xor_sync(0xffffffffu, acc, o);
        if (lane == 0) dp[b * INT_DIM + i] = acc;
    }
}

// ---------------------------------------------------------------------------
// K1: scores + fused partial-softmax/partial-context (round-12 mainloop).
// CTA = 64 rows x 256 n, 256 thr, 2 CTAs/SM. A resident (8 chunk buffers),
// B 3-stage cp.async(.ca) pipeline.
// ---------------------------------------------------------------------------
__global__ void __launch_bounds__(NTHR, 2)
scores_mma_kernel(const float* __restrict__ enc,
                  const __half* __restrict__ w1h,
                  const float* __restrict__ dp,
                  const float* __restrict__ v,
                  float* __restrict__ scores,
                  float* __restrict__ pm,
                  float* __restrict__ pz,
                  float* __restrict__ pctx,
                  int T) {
    extern __shared__ unsigned sm[];          // A0..A7 | B0..B2
    __shared__ float dps[INT_DIM], vs[INT_DIM], ssc[MT];
    __shared__ float redm[2], redz[2], mc_sh;

    const int tid  = threadIdx.x;
    const int wid  = tid >> 5;
    const int lane = tid & 31;
    const int t    = lane & 3;
    const int m0   = (wid & 1) * 32;
    const int nb   = (wid >> 1) * 64;
    const int bid  = blockIdx.x;
    const long long row0 = (long long)bid * MT;
    const int b = (int)(row0 / T);

    dps[tid] = dp[b * INT_DIM + tid];
    vs[tid]  = __ldg(v + tid);
    if (tid < MT) ssc[tid] = 0.f;

    const unsigned smem_base = s2u(sm);

    const unsigned a_lane_off = (unsigned)((m0 + (lane & 15)) * P + ((lane >> 4) << 2));
    const unsigned b_lane_off = (unsigned)((nb + ((lane >> 4) & 1) * 8 + (lane & 7)) * P
                                           + ((lane >> 3) & 1) * 4);

    const int ar = tid >> 2;                  // A staging: row (0..63)
    const int aq = tid & 3;                   // A staging: 16B quarter of row

    auto stageB = [&](int c) {
        const int kc = c * KC;
        const unsigned bb = smem_base + (NCHUNK * ASZ + (c % 3) * BSZ) * 4;
#pragma unroll
        for (int i = tid; i < NT * 4; i += NTHR) {
            int n = i >> 2, q = i & 3;
            cp16ca(bb + (n * P + q * 4) * 4, w1h + n * ENC_DIM + kc + q * 8);
        }
    };

    float4 fr[2];                              // A prefetch regs (8 floats)
    auto ldgA = [&](int c) {
        const float4* src = reinterpret_cast<const float4*>(
            enc + (row0 + ar) * ENC_DIM + c * KC + aq * 8);
        fr[0] = src[0]; fr[1] = src[1];
    };
    auto stsA = [&](int c) {                   // A buffer c is unique: no reuse
        __half2 h0 = __floats2half2_rn(fr[0].x, fr[0].y);
        __half2 h1 = __floats2half2_rn(fr[0].z, fr[0].w);
        __half2 h2 = __floats2half2_rn(fr[1].x, fr[1].y);
        __half2 h3 = __floats2half2_rn(fr[1].z, fr[1].w);
        uint4 w = make_uint4(*reinterpret_cast<uint32_t*>(&h0),
                             *reinterpret_cast<uint32_t*>(&h1),
                             *reinterpret_cast<uint32_t*>(&h2),
                             *reinterpret_cast<uint32_t*>(&h3));
        *reinterpret_cast<uint4*>(sm + c * ASZ + ar * P + aq * 4) = w;
    };

    float d[2][8][4];
#pragma unroll
    for (int h = 0; h < 2; ++h)
#pragma unroll
        for (int j = 0; j < 8; ++j)
#pragma unroll
            for (int q = 0; q < 4; ++q) d[h][j][q] = 0.f;

    // prologue: B0,B1 in flight; A0,A1 staged; regs hold A2
    stageB(0); cp_commit();
    stageB(1); cp_commit();
    ldgA(0); stsA(0);
    ldgA(1); stsA(1);
    ldgA(2);

    for (int c = 0; c < NCHUNK; ++c) {
        if (c < NCHUNK - 1) cp_wait<1>(); else cp_wait<0>();
        __syncthreads();          // B(c) + A(c) visible; B buf (c+2)%3 free

        if (c + 2 < NCHUNK) {
            stsA(c + 2);          // from regs loaded last iter
            stageB(c + 2); cp_commit();
            if (c + 3 < NCHUNK) ldgA(c + 3);
        }

        const unsigned abase = smem_base + (c * ASZ) * 4 + a_lane_off * 4;
        const unsigned bbase = smem_base + (NCHUNK * ASZ + (c % 3) * BSZ) * 4
                               + b_lane_off * 4;

#pragma unroll
        for (int s = 0; s < NKS; ++s) {
            unsigned a[2][4];
            ldsm4(a[0], abase + (s * 8) * 4);
            ldsm4(a[1], abase + (16 * P + s * 8) * 4);
#pragma unroll
            for (int jp = 0; jp < 4; ++jp) {
                unsigned bb[4];
                ldsm4(bb, bbase + (jp * 16 * P + s * 8) * 4);
                mma_f16(d[0][2 * jp],     a[0], bb[0], bb[1]);
                mma_f16(d[1][2 * jp],     a[1], bb[0], bb[1]);
                mma_f16(d[0][2 * jp + 1], a[0], bb[2], bb[3]);
                mma_f16(d[1][2 * jp + 1], a[1], bb[2], bb[3]);
            }
        }
    }

    // Score epilogue: +dec_proj, tanh.approx, *v, warp-reduce, smem combine
    const int g = lane >> 2;
#pragma unroll
    for (int h = 0; h < 2; ++h) {
        float s0 = 0.f, s1 = 0.f;
#pragma unroll
        for (int j = 0; j < 8; ++j) {
            const int n0 = nb + 8 * j + 2 * t;
            const float vv0 = vs[n0],  vv1 = vs[n0 + 1];
            const float dd0 = dps[n0], dd1 = dps[n0 + 1];
            s0 += vv0 * tanha(d[h][j][0] + dd0) + vv1 * tanha(d[h][j][1] + dd1);
            s1 += vv0 * tanha(d[h][j][2] + dd0) + vv1 * tanha(d[h][j][3] + dd1);
        }
        s0 += __shfl_xor_sync(0xffffffffu, s0, 1);
        s0 += __shfl_xor_sync(0xffffffffu, s0, 2);
        s1 += __shfl_xor_sync(0xffffffffu, s1, 1);
        s1 += __shfl_xor_sync(0xffffffffu, s1, 2);
        if (t == 0) {
            atomicAdd(&ssc[m0 + 16 * h + g], s0);
            atomicAdd(&ssc[m0 + 16 * h + 8 + g], s1);
        }
    }
    __syncthreads();
    if (tid < MT) scores[row0 + tid] = ssc[tid];

    // ---- fused partial softmax + partial context (flash-style) ----
    if (tid < MT) {
        float s = ssc[tid];
#pragma unroll
        for (int o = 16; o; o >>= 1) s = fmaxf(s, __shfl_xor_sync(0xffffffffu, s, o));
        if (lane == 0) redm[wid] = s;
    }
    __syncthreads();
    if (tid == 0) mc_sh = fmaxf(redm[0], redm[1]);
    __syncthreads();
    const float m_c = mc_sh;

    if (tid < MT) {
        float p = expf(ssc[tid] - m_c);
        ssc[tid] = p;
        float z = p;
#pragma unroll
        for (int o = 16; o; o >>= 1) z += __shfl_xor_sync(0xffffffffu, z, o);
        if (lane == 0) redz[wid] = z;
    }
    __syncthreads();
    if (tid == 0) {
        pm[bid] = m_c;
        pz[bid] = redz[0] + redz[1];
    }

    // partial context: thread owns column e = tid; reads resident fp16 A
    {
        const int ch   = tid >> 5;             // chunk buffer holding k = e
        const int woff = (tid & 31) >> 1;      // word within row
        const int hh   = tid & 1;
        const unsigned* abuf = sm + ch * ASZ + woff;
        float acc = 0.f;
#pragma unroll 8
        for (int r = 0; r < MT; ++r) {
            unsigned w = abuf[r * P];
            __half2 hx = *reinterpret_cast<__half2*>(&w);
            float x = hh ? __high2float(hx) : __low2float(hx);
            acc = fmaf(ssc[r], x, acc);
        }
        pctx[(long long)bid * ENC_DIM + tid] = acc;
    }
}

// ---------------------------------------------------------------------------
// K2: combine partials per batch (exact flash rescale) -> context + {m, Z}
// ---------------------------------------------------------------------------
__global__ void combine_kernel(const float* __restrict__ pm,
                               const float* __restrict__ pz,
                               const float* __restrict__ pctx,
                               float* __restrict__ out,
                               float* __restrict__ mz,
                               int cpb) {
    __shared__ float mc[MAXCPB], wc[MAXCPB];
    __shared__ float m_sh, z_sh;
    const int b = blockIdx.x;
    const int tid = threadIdx.x;

    if (tid < cpb) mc[tid] = pm[b * cpb + tid];
    __syncthreads();
    if (tid == 0) {
        float m = mc[0];
        for (int c = 1; c < cpb; ++c) m = fmaxf(m, mc[c]);
        m_sh = m;
    }
    __syncthreads();
    const float m = m_sh;
    if (tid < cpb) wc[tid] = expf(mc[tid] - m);
    __syncthreads();
    if (tid == 0) {
        float z = 0.f;
        for (int c = 0; c < cpb; ++c) z += pz[b * cpb + c] * wc[c];
        z_sh = z;
        mz[2 * b] = m;
        mz[2 * b + 1] = z;
    }
    __syncthreads();
    const float invZ = 1.f / z_sh;

    float acc = 0.f;
    for (int c = 0; c < cpb; ++c)
        acc = fmaf(pctx[((long long)(b * cpb + c)) * ENC_DIM + tid], wc[c], acc);
    out[b * ENC_DIM + tid] = acc * invZ;
}

// ---------------------------------------------------------------------------
// K3: probs = exp(score - m) / Z. grid (B, 8) for latency.
// ---------------------------------------------------------------------------
__global__ void probs_kernel(const float* __restrict__ scores,
                             const float* __restrict__ mz,
                             float* __restrict__ out,
                             int B, int T) {
    const int b = blockIdx.x;
    const int seg = blockIdx.y;
    const int tid = threadIdx.x;
    const float m = mz[2 * b];
    const float inv = 1.f / mz[2 * b + 1];
    const int t = seg * 256 + tid;
    float* probs = out + (long long)B * ENC_DIM;
    if (t < T)
        probs[(long long)b * T + t] = expf(scores[b * T + t] - m) * inv;
}

// ---------------------------------------------------------------------------
extern "C" void kernel_launch(void* const* d_in, const int* in_sizes, int n_in,
                              void* d_out, int out_size) {
    const float* enc = (const float*)d_in[0];   // [B,T,256]
    const float* dec = (const float*)d_in[1];   // [B,256]
    const float* w1  = (const float*)d_in[2];   // [256,256]
    const float* w2  = (const float*)d_in[3];   // [256,256]
    const float* v   = (const float*)d_in[4];   // [1,256]
    float* out = (float*)d_out;

    const int B = in_sizes[1] / ENC_DIM;                 // 64
    const int T = in_sizes[0] / (B * ENC_DIM);           // 2048
    const int cpb = T / MT;                              // 32

    float*  dp_ptr;     cudaGetSymbolAddress((void**)&dp_ptr, g_dp);
    float*  scores_ptr; cudaGetSymbolAddress((void**)&scores_ptr, g_scores);
    __half* w1h_ptr;    cudaGetSymbolAddress((void**)&w1h_ptr, g_w1h);
    float*  pm_ptr;     cudaGetSymbolAddress((void**)&pm_ptr, g_pm);
    float*  pz_ptr;     cudaGetSymbolAddress((void**)&pz_ptr, g_pz);
    float*  pctx_ptr;   cudaGetSymbolAddress((void**)&pctx_ptr, g_pctx);
    float*  mz_ptr;     cudaGetSymbolAddress((void**)&mz_ptr, g_mz);

    cudaFuncSetAttribute(scores_mma_kernel,
                         cudaFuncAttributeMaxDynamicSharedMemorySize, DYN_BYTES);

    prep_kernel<<<B, 256>>>(dec, w2, w1, w1h_ptr, dp_ptr);
    scores_mma_kernel<<<(B * T) / MT, NTHR, DYN_BYTES>>>(
        enc, w1h_ptr, dp_ptr, v, scores_ptr, pm_ptr, pz_ptr, pctx_ptr, T);
    combine_kernel<<<B, 256>>>(pm_ptr, pz_ptr, pctx_ptr, out, mz_ptr, cpb);
    probs_kernel<<<dim3(B, (T + 255) / 256), 256>>>(scores_ptr, mz_ptr, out, B, T);
}

// round 15
// speedup vs baseline: 1.1209x; 1.1209x over previous
#include <cuda_runtime.h>
#include <cuda_fp16.h>
#include <cuda_bf16.h>
#include <math_constants.h>
#include <cstdint>

#define ENC_DIM 256
#define INT_DIM 256
#define MT 64                    // rows per tile
#define NTHR 512
#define MAXCPB 32                // tiles per batch (T/MT)
#define BBYTES 131072            // resident B: 4 slabs x [256 rows][128B]
#define ATILE 32768              // one A tile: 4 slabs x [64 rows][128B]
#define DYN_BYTES (BBYTES + 2 * ATILE)   // 196608 -> 1 CTA/SM
#define SWZ(x) ((x) ^ (((x) >> 3) & 0x70))

// Scratch (allocation-free rule: __device__ globals)
__device__ float  g_dp[64 * INT_DIM];          // dec_proj [B, I]
__device__ float  g_scores[64 * 2048];         // scores   [B, T]
__device__ __half g_w1h[INT_DIM * ENC_DIM];    // w1 as fp16, [n][k]
__device__ float  g_pm[2048];                  // per-tile local max
__device__ float  g_pz[2048];                  // per-tile local exp-sum
__device__ float  g_pctx[2048 * ENC_DIM];      // per-tile partial context
__device__ float  g_mz[128];                   // per-batch {m, Z}

// ---------------------------------------------------------------------------
// helpers
// ---------------------------------------------------------------------------
__device__ __forceinline__ float tanha(float x) {
    float y;
    asm("tanh.approx.f32 %0, %1;" : "=f"(y) : "f"(x));
    return y;
}
__device__ __forceinline__ void cp16(unsigned dst_s, const void* src) {
    asm volatile("cp.async.cg.shared.global [%0], [%1], 16;"
                 :: "r"(dst_s), "l"(src) : "memory");
}
__device__ __forceinline__ void cp_commit() {
    asm volatile("cp.async.commit_group;" ::: "memory");
}
template <int N>
__device__ __forceinline__ void cp_wait() {
    asm volatile("cp.async.wait_group %0;" :: "n"(N) : "memory");
}
__device__ __forceinline__ unsigned s2u(const void* p) {
    return (unsigned)__cvta_generic_to_shared(p);
}
__device__ __forceinline__ void ldsm4(unsigned r[4], unsigned addr) {
    asm volatile("ldmatrix.sync.aligned.m8n8.x4.shared.b16 "
                 "{%0,%1,%2,%3}, [%4];"
                 : "=r"(r[0]), "=r"(r[1]), "=r"(r[2]), "=r"(r[3])
                 : "r"(addr));
}
__device__ __forceinline__ void mma_f16(float d[4], const unsigned a[4],
                                        unsigned b0, unsigned b1) {
    asm volatile(
        "mma.sync.aligned.m16n8k16.row.col.f32.f16.f16.f32 "
        "{%0,%1,%2,%3}, {%4,%5,%6,%7}, {%8,%9}, {%0,%1,%2,%3};"
        : "+f"(d[0]), "+f"(d[1]), "+f"(d[2]), "+f"(d[3])
        : "r"(a[0]), "r"(a[1]), "r"(a[2]), "r"(a[3]), "r"(b0), "r"(b1));
}
__device__ __forceinline__ uint32_t h2u(__half2 h) {
    return *reinterpret_cast<uint32_t*>(&h);
}

// ---------------------------------------------------------------------------
// K0: fused prep (dec_proj + w1 -> fp16). grid = 64 x 256.
// ---------------------------------------------------------------------------
__global__ void prep_kernel(const float* __restrict__ dec,
                            const float* __restrict__ w2,
                            const float* __restrict__ w1,
                            __half* __restrict__ w1h,
                            float* __restrict__ dp) {
    __shared__ float ds[ENC_DIM];
    const int b = blockIdx.x;
    const int tid = threadIdx.x;
    const int lane = tid & 31, wid = tid >> 5;

    ds[tid] = dec[b * ENC_DIM + tid];

    {
        const int base = b * 1024 + tid * 4;
        float4 wv = *reinterpret_cast<const float4*>(w1 + base);
        __half2 p0 = __floats2half2_rn(wv.x, wv.y);
        __half2 p1 = __floats2half2_rn(wv.z, wv.w);
        *reinterpret_cast<uint2*>(w1h + base) = make_uint2(h2u(p0), h2u(p1));
    }
    __syncthreads();

#pragma unroll 4
    for (int ii = 0; ii < 32; ++ii) {
        const int i = wid * 32 + ii;
        float acc = 0.f;
#pragma unroll
        for (int kk = 0; kk < 8; ++kk) {
            const int k = kk * 32 + lane;
            acc = fmaf(__ldg(w2 + i * ENC_DIM + k), ds[k], acc);
        }
#pragma unroll
        for (int o = 16; o; o >>= 1) acc += __shfl_xor_sync(0xffffffffu, acc, o);
        if (lane == 0) dp[b * INT_DIM + i] = acc;
    }
}

// ---------------------------------------------------------------------------
// K1: persistent scores + fused partial-softmax/partial-context.
// Grid = #SMs, 512 threads, 1 CTA/SM. B (w1h) fully resident in smem
// (4 SW128-swizzled slabs of [256 rows][128B]); A double-buffered per tile.
// CTA loops tiles bid, bid+G, ... Per tile: 16 straight k16 mma steps.
// ---------------------------------------------------------------------------
__global__ void __launch_bounds__(NTHR, 1)
scores_mma_kernel(const float* __restrict__ enc,
                  const __half* __restrict__ w1h,
                  const float* __restrict__ dp,
                  const float* __restrict__ v,
                  float* __restrict__ scores,
                  float* __restrict__ pm,
                  float* __restrict__ pz,
                  float* __restrict__ pctx,
                  int T, int nTiles) {
    extern __shared__ unsigned char smb[];    // [B: 131072][A: 2 x 32768]
    __shared__ float dps[INT_DIM], vs[INT_DIM], ssc[MT], ctx2[NTHR];

    const int tid  = threadIdx.x;
    const int wid  = tid >> 5;
    const int lane = tid & 31;
    const int t    = lane & 3;
    const int g    = lane >> 2;
    const int G    = gridDim.x;

    // mma lane constants (layout identical to proven pitch version, swizzled)
    const int m0 = (wid & 1) * 32;
    const int nb = (wid >> 1) * 32;
    const int rowa = m0 + (lane & 15);
    const unsigned hha = (unsigned)(lane >> 4);
    const unsigned r7a = (unsigned)(rowa & 7);
    const int rowb = nb + ((lane >> 4) & 1) * 8 + (lane & 7);
    const unsigned hhb = (unsigned)((lane >> 3) & 1);
    const unsigned r7b = (unsigned)(rowb & 7);

    const unsigned smem_u = s2u(smb);

    // A staging constants: thread -> (row, 16B-unit)
    const int sr = tid >> 3;                  // row 0..63
    const int su = tid & 7;                   // unit 0..7

    // ---- load resident B (swizzled slabs) ----
    for (int i = tid; i < 8192; i += NTHR) {
        int ch = i >> 11, n = (i >> 3) & 255, u = i & 7;
        unsigned off = (unsigned)(ch * 32768) + SWZ((unsigned)(n * 128 + u * 16));
        cp16(smem_u + off, w1h + n * 256 + ch * 64 + u * 8);
    }
    cp_commit();

    if (tid < INT_DIM) vs[tid] = __ldg(v + tid);
    if (tid < MT) ssc[tid] = 0.f;

    float4 fr[8];                              // A prefetch (32 regs)
    auto ldgA = [&](long long r0) {
#pragma unroll
        for (int sl = 0; sl < 4; ++sl) {
            const float4* s4 = reinterpret_cast<const float4*>(
                enc + (r0 + sr) * ENC_DIM + sl * 64 + su * 8);
            fr[2 * sl]     = s4[0];
            fr[2 * sl + 1] = s4[1];
        }
    };
    auto stsA = [&](int buf) {
#pragma unroll
        for (int sl = 0; sl < 4; ++sl) {
            __half2 h0 = __floats2half2_rn(fr[2*sl].x,   fr[2*sl].y);
            __half2 h1 = __floats2half2_rn(fr[2*sl].z,   fr[2*sl].w);
            __half2 h2 = __floats2half2_rn(fr[2*sl+1].x, fr[2*sl+1].y);
            __half2 h3 = __floats2half2_rn(fr[2*sl+1].z, fr[2*sl+1].w);
            unsigned off = (unsigned)(BBYTES + buf * ATILE + sl * 8192)
                         + SWZ((unsigned)(sr * 128 + su * 16));
            *reinterpret_cast<uint4*>(smb + off) =
                make_uint4(h2u(h0), h2u(h1), h2u(h2), h2u(h3));
        }
    };

    // ---- prologue: A(tile0) staged to buf0; fr holds A(tile0+G) ----
    int tile = blockIdx.x;
    ldgA((long long)tile * MT);
    stsA(0);
    if (tile + G < nTiles) ldgA((long long)(tile + G) * MT);
    if (tid < INT_DIM)
        dps[tid] = dp[(int)(((long long)tile * MT) / T) * INT_DIM + tid];
    cp_wait<0>();
    __syncthreads();

    for (int it = 0; tile < nTiles; tile += G, ++it) {
        const int buf = it & 1;
        const long long row0 = (long long)tile * MT;
        const bool hn = (tile + G) < nTiles;

        if (hn) stsA(buf ^ 1);                 // A(next) from regs
        if ((tile + 2 * G) < nTiles) ldgA((long long)(tile + 2 * G) * MT);

        float d[2][4][4];
#pragma unroll
        for (int h = 0; h < 2; ++h)
#pragma unroll
            for (int j = 0; j < 4; ++j)
#pragma unroll
                for (int q = 0; q < 4; ++q) d[h][j][q] = 0.f;

        // ---- 16 straight k16 steps against resident B ----
#pragma unroll
        for (int ch = 0; ch < 4; ++ch) {
            const unsigned Asl = smem_u + BBYTES + buf * ATILE + ch * 8192;
            const unsigned Bsl = smem_u + ch * 32768;
#pragma unroll
            for (int sp = 0; sp < 4; ++sp) {
                unsigned ua = (((unsigned)(sp << 1)) | hha) ^ r7a;
                unsigned a0a = Asl + (unsigned)(rowa * 128) + (ua << 4);
                unsigned a[2][4];
                ldsm4(a[0], a0a);
                ldsm4(a[1], a0a + 2048);
                unsigned ub = (((unsigned)(sp << 1)) | hhb) ^ r7b;
                unsigned b0a = Bsl + (unsigned)(rowb * 128) + (ub << 4);
                unsigned bb0[4], bb1[4];
                ldsm4(bb0, b0a);
                ldsm4(bb1, b0a + 2048);
                mma_f16(d[0][0], a[0], bb0[0], bb0[1]);
                mma_f16(d[1][0], a[1], bb0[0], bb0[1]);
                mma_f16(d[0][1], a[0], bb0[2], bb0[3]);
                mma_f16(d[1][1], a[1], bb0[2], bb0[3]);
                mma_f16(d[0][2], a[0], bb1[0], bb1[1]);
                mma_f16(d[1][2], a[1], bb1[0], bb1[1]);
                mma_f16(d[0][3], a[0], bb1[2], bb1[3]);
                mma_f16(d[1][3], a[1], bb1[2], bb1[3]);
            }
        }

        // ---- score epilogue: +dec_proj, tanh.approx, *v, reduce ----
#pragma unroll
        for (int h = 0; h < 2; ++h) {
            float s0 = 0.f, s1 = 0.f;
#pragma unroll
            for (int j = 0; j < 4; ++j) {
                const int n0 = nb + 8 * j + 2 * t;
                const float vv0 = vs[n0],  vv1 = vs[n0 + 1];
                const float dd0 = dps[n0], dd1 = dps[n0 + 1];
                s0 += vv0 * tanha(d[h][j][0] + dd0) + vv1 * tanha(d[h][j][1] + dd1);
                s1 += vv0 * tanha(d[h][j][2] + dd0) + vv1 * tanha(d[h][j][3] + dd1);
            }
            s0 += __shfl_xor_sync(0xffffffffu, s0, 1);
            s0 += __shfl_xor_sync(0xffffffffu, s0, 2);
            s1 += __shfl_xor_sync(0xffffffffu, s1, 1);
            s1 += __shfl_xor_sync(0xffffffffu, s1, 2);
            if (t == 0) {
                atomicAdd(&ssc[m0 + 16 * h + g], s0);
                atomicAdd(&ssc[m0 + 16 * h + 8 + g], s1);
            }
        }
        __syncthreads();                       // ssc complete

        // ---- warp0: raw scores out, softmax partials ----
        if (tid < 32) {
            float sA = ssc[lane], sB = ssc[lane + 32];
            scores[row0 + lane]      = sA;
            scores[row0 + 32 + lane] = sB;
            float mx = fmaxf(sA, sB);
#pragma unroll
            for (int o = 16; o; o >>= 1)
                mx = fmaxf(mx, __shfl_xor_sync(0xffffffffu, mx, o));
            float pA = expf(sA - mx), pB = expf(sB - mx);
            ssc[lane] = pA; ssc[lane + 32] = pB;
            float z = pA + pB;
#pragma unroll
            for (int o = 16; o; o >>= 1) z += __shfl_xor_sync(0xffffffffu, z, o);
            if (lane == 0) { pm[tile] = mx; pz[tile] = z; }
        }
        __syncthreads();                       // weights in ssc

        // ---- partial context from resident fp16 A (swizzled reads) ----
        {
            const int e = tid & 255, half = tid >> 8;
            const int ech = e >> 6, hw = e & 63, u = hw >> 3;
            const unsigned lo = (unsigned)((hw & 7) * 2);
            const unsigned char* abase = smb + BBYTES + buf * ATILE + ech * 8192;
            float acc = 0.f;
            const int rbeg = half * 32;
#pragma unroll 8
            for (int rr = 0; rr < 32; ++rr) {
                const int r = rbeg + rr;
                unsigned off = (unsigned)(r * 128)
                             + ((((unsigned)u) ^ ((unsigned)(r & 7))) << 4) + lo;
                __half hv = *reinterpret_cast<const __half*>(abase + off);
                acc = fmaf(ssc[r], __half2float(hv), acc);
            }
            ctx2[tid] = acc;
        }
        __syncthreads();
        if (tid < 256) pctx[(long long)tile * ENC_DIM + tid] = ctx2[tid] + ctx2[tid + 256];
        if (tid >= 64 && tid < 128) ssc[tid - 64] = 0.f;
        if (hn && tid < INT_DIM)               // dps for next tile
            dps[tid] = dp[(int)(((long long)(tile + G) * MT) / T) * INT_DIM + tid];
        __syncthreads();                       // tile boundary
    }
}

// ---------------------------------------------------------------------------
// K2: combine partials per batch (exact flash rescale) -> context + {m, Z}
// ---------------------------------------------------------------------------
__global__ void combine_kernel(const float* __restrict__ pm,
                               const float* __restrict__ pz,
                               const float* __restrict__ pctx,
                               float* __restrict__ out,
                               float* __restrict__ mz,
                               int cpb) {
    __shared__ float mc[MAXCPB], wc[MAXCPB];
    __shared__ float m_sh, z_sh;
    const int b = blockIdx.x;
    const int tid = threadIdx.x;

    if (tid < cpb) mc[tid] = pm[b * cpb + tid];
    __syncthreads();
    if (tid == 0) {
        float m = mc[0];
        for (int c = 1; c < cpb; ++c) m = fmaxf(m, mc[c]);
        m_sh = m;
    }
    __syncthreads();
    const float m = m_sh;
    if (tid < cpb) wc[tid] = expf(mc[tid] - m);
    __syncthreads();
    if (tid == 0) {
        float z = 0.f;
        for (int c = 0; c < cpb; ++c) z += pz[b * cpb + c] * wc[c];
        z_sh = z;
        mz[2 * b] = m;
        mz[2 * b + 1] = z;
    }
    __syncthreads();
    const float invZ = 1.f / z_sh;

    float acc = 0.f;
    for (int c = 0; c < cpb; ++c)
        acc = fmaf(pctx[((long long)(b * cpb + c)) * ENC_DIM + tid], wc[c], acc);
    out[b * ENC_DIM + tid] = acc * invZ;
}

// ---------------------------------------------------------------------------
// K3: probs = exp(score - m) / Z. grid (B, T/256).
// ---------------------------------------------------------------------------
__global__ void probs_kernel(const float* __restrict__ scores,
                             const float* __restrict__ mz,
                             float* __restrict__ out,
                             int B, int T) {
    const int b = blockIdx.x;
    const int seg = blockIdx.y;
    const int tid = threadIdx.x;
    const float m = mz[2 * b];
    const float inv = 1.f / mz[2 * b + 1];
    const int t = seg * 256 + tid;
    float* probs = out + (long long)B * ENC_DIM;
    if (t < T)
        probs[(long long)b * T + t] = expf(scores[b * T + t] - m) * inv;
}

// ---------------------------------------------------------------------------
extern "C" void kernel_launch(void* const* d_in, const int* in_sizes, int n_in,
                              void* d_out, int out_size) {
    const float* enc = (const float*)d_in[0];   // [B,T,256]
    const float* dec = (const float*)d_in[1];   // [B,256]
    const float* w1  = (const float*)d_in[2];   // [256,256]
    const float* w2  = (const float*)d_in[3];   // [256,256]
    const float* v   = (const float*)d_in[4];   // [1,256]
    float* out = (float*)d_out;

    const int B = in_sizes[1] / ENC_DIM;                 // 64
    const int T = in_sizes[0] / (B * ENC_DIM);           // 2048
    const int cpb = T / MT;                              // 32
    const int nTiles = (B * T) / MT;                     // 2048

    int nsm = 148;
    cudaDeviceGetAttribute(&nsm, cudaDevAttrMultiProcessorCount, 0);

    float*  dp_ptr;     cudaGetSymbolAddress((void**)&dp_ptr, g_dp);
    float*  scores_ptr; cudaGetSymbolAddress((void**)&scores_ptr, g_scores);
    __half* w1h_ptr;    cudaGetSymbolAddress((void**)&w1h_ptr, g_w1h);
    float*  pm_ptr;     cudaGetSymbolAddress((void**)&pm_ptr, g_pm);
    float*  pz_ptr;     cudaGetSymbolAddress((void**)&pz_ptr, g_pz);
    float*  pctx_ptr;   cudaGetSymbolAddress((void**)&pctx_ptr, g_pctx);
    float*  mz_ptr;     cudaGetSymbolAddress((void**)&mz_ptr, g_mz);

    cudaFuncSetAttribute(scores_mma_kernel,
                         cudaFuncAttributeMaxDynamicSharedMemorySize, DYN_BYTES);

    prep_kernel<<<B, 256>>>(dec, w2, w1, w1h_ptr, dp_ptr);
    scores_mma_kernel<<<nsm, NTHR, DYN_BYTES>>>(
        enc, w1h_ptr, dp_ptr, v, scores_ptr, pm_ptr, pz_ptr, pctx_ptr, T, nTiles);
    combine_kernel<<<B, 256>>>(pm_ptr, pz_ptr, pctx_ptr, out, mz_ptr, cpb);
    probs_kernel<<<dim3(B, (T + 255) / 256), 256>>>(scores_ptr, mz_ptr, out, B, T);
}

// round 16
// speedup vs baseline: 1.1443x; 1.0208x over previous
#include <cuda_runtime.h>
#include <cuda_fp16.h>
#include <cuda_bf16.h>
#include <math_constants.h>
#include <cstdint>

#define ENC_DIM 256
#define INT_DIM 256
#define MT 64                   // rows per CTA (M)
#define NT 256                  // hidden per CTA (N)
#define KC 32                   // k per chunk
#define NCHUNK (ENC_DIM / KC)   // 8
#define NKS (KC / 16)           // 2 k16 steps per chunk
#define P 20                    // smem pitch in u32 words (16 used + 4 pad)
#define ASZ (MT * P)            // 1280 words (one A chunk buffer)
#define BSZ (NT * P)            // 5120 words (one B stage)
#define BSTG 3                  // B pipeline stages
#define DYN_BYTES ((NCHUNK * ASZ + BSTG * BSZ) * 4)   // 102400 -> 2 CTAs/SM
#define NTHR 256
#define MAXCPB 32               // chunks per batch (T/MT)

// Scratch (allocation-free rule: __device__ globals)
__device__ float  g_dp[64 * INT_DIM];          // dec_proj [B, I]
__device__ float  g_scores[64 * 2048];         // scores   [B, T]
__device__ __half g_w1h[INT_DIM * ENC_DIM];    // w1 as fp16, [n][k]
__device__ float  g_pm[2048];                  // per-CTA local max
__device__ float  g_pz[2048];                  // per-CTA local exp-sum
__device__ float  g_pctx[2048 * ENC_DIM];      // per-CTA partial context

// ---------------------------------------------------------------------------
// helpers
// ---------------------------------------------------------------------------
__device__ __forceinline__ float tanha(float x) {
    float y;
    asm("tanh.approx.f32 %0, %1;" : "=f"(y) : "f"(x));
    return y;
}
__device__ __forceinline__ void cp16(unsigned dst_s, const void* src) {
    asm volatile("cp.async.cg.shared.global [%0], [%1], 16;"
                 :: "r"(dst_s), "l"(src) : "memory");
}
__device__ __forceinline__ void cp_commit() {
    asm volatile("cp.async.commit_group;" ::: "memory");
}
template <int N>
__device__ __forceinline__ void cp_wait() {
    asm volatile("cp.async.wait_group %0;" :: "n"(N) : "memory");
}
__device__ __forceinline__ unsigned s2u(const void* p) {
    return (unsigned)__cvta_generic_to_shared(p);
}
__device__ __forceinline__ void ldsm4(unsigned r[4], unsigned addr) {
    asm volatile("ldmatrix.sync.aligned.m8n8.x4.shared.b16 "
                 "{%0,%1,%2,%3}, [%4];"
                 : "=r"(r[0]), "=r"(r[1]), "=r"(r[2]), "=r"(r[3])
                 : "r"(addr));
}
__device__ __forceinline__ void mma_f16(float d[4], const unsigned a[4],
                                        unsigned b0, unsigned b1) {
    asm volatile(
        "mma.sync.aligned.m16n8k16.row.col.f32.f16.f16.f32 "
        "{%0,%1,%2,%3}, {%4,%5,%6,%7}, {%8,%9}, {%0,%1,%2,%3};"
        : "+f"(d[0]), "+f"(d[1]), "+f"(d[2]), "+f"(d[3])
        : "r"(a[0]), "r"(a[1]), "r"(a[2]), "r"(a[3]), "r"(b0), "r"(b1));
}

// ---------------------------------------------------------------------------
// K0: prep, parallel halves. grid = 128 x 256.
//  blocks [0,64):  dec_proj[b, :] (warp-per-32-outputs coalesced reduction)
//  blocks [64,128): w1 -> fp16 slice (1024 elements per block)
// ---------------------------------------------------------------------------
__global__ void prep_kernel(const float* __restrict__ dec,
                            const float* __restrict__ w2,
                            const float* __restrict__ w1,
                            __half* __restrict__ w1h,
                            float* __restrict__ dp) {
    const int tid = threadIdx.x;

    if (blockIdx.x >= 64) {                    // w1 -> fp16 conversion
        const int base = (blockIdx.x - 64) * 1024 + tid * 4;
        float4 wv = *reinterpret_cast<const float4*>(w1 + base);
        __half2 p0 = __floats2half2_rn(wv.x, wv.y);
        __half2 p1 = __floats2half2_rn(wv.z, wv.w);
        uint2 pk = make_uint2(*reinterpret_cast<uint32_t*>(&p0),
                              *reinterpret_cast<uint32_t*>(&p1));
        *reinterpret_cast<uint2*>(w1h + base) = pk;
        return;
    }

    __shared__ float ds[ENC_DIM];
    const int b = blockIdx.x;
    const int lane = tid & 31, wid = tid >> 5;

    ds[tid] = dec[b * ENC_DIM + tid];
    __syncthreads();

#pragma unroll 4
    for (int ii = 0; ii < 32; ++ii) {
        const int i = wid * 32 + ii;
        float acc = 0.f;
#pragma unroll
        for (int kk = 0; kk < 8; ++kk) {
            const int k = kk * 32 + lane;
            acc = fmaf(__ldg(w2 + i * ENC_DIM + k), ds[k], acc);
        }
#pragma unroll
        for (int o = 16; o; o >>= 1) acc += __shfl_xor_sync(0xffffffffu, acc, o);
        if (lane == 0) dp[b * INT_DIM + i] = acc;
    }
}

// ---------------------------------------------------------------------------
// K1: scores + fused partial-softmax/partial-context (round-12 mainloop).
// CTA = 64 rows x 256 n, 256 thr, 2 CTAs/SM. A resident (8 chunk buffers),
// B 3-stage cp.async pipeline.
// ---------------------------------------------------------------------------
__global__ void __launch_bounds__(NTHR, 2)
scores_mma_kernel(const float* __restrict__ enc,
                  const __half* __restrict__ w1h,
                  const float* __restrict__ dp,
                  const float* __restrict__ v,
                  float* __restrict__ scores,
                  float* __restrict__ pm,
                  float* __restrict__ pz,
                  float* __restrict__ pctx,
                  int T) {
    extern __shared__ unsigned sm[];          // A0..A7 | B0..B2
    __shared__ float dps[INT_DIM], vs[INT_DIM], ssc[MT];
    __shared__ float redm[2], redz[2], mc_sh;

    const int tid  = threadIdx.x;
    const int wid  = tid >> 5;
    const int lane = tid & 31;
    const int t    = lane & 3;
    const int m0   = (wid & 1) * 32;
    const int nb   = (wid >> 1) * 64;
    const int bid  = blockIdx.x;
    const long long row0 = (long long)bid * MT;
    const int b = (int)(row0 / T);

    dps[tid] = dp[b * INT_DIM + tid];
    vs[tid]  = __ldg(v + tid);
    if (tid < MT) ssc[tid] = 0.f;

    const unsigned smem_base = s2u(sm);

    const unsigned a_lane_off = (unsigned)((m0 + (lane & 15)) * P + ((lane >> 4) << 2));
    const unsigned b_lane_off = (unsigned)((nb + ((lane >> 4) & 1) * 8 + (lane & 7)) * P
                                           + ((lane >> 3) & 1) * 4);

    const int ar = tid >> 2;                  // A staging: row (0..63)
    const int aq = tid & 3;                   // A staging: 16B quarter of row

    auto stageB = [&](int c) {
        const int kc = c * KC;
        const unsigned bb = smem_base + (NCHUNK * ASZ + (c % 3) * BSZ) * 4;
#pragma unroll
        for (int i = tid; i < NT * 4; i += NTHR) {
            int n = i >> 2, q = i & 3;
            cp16(bb + (n * P + q * 4) * 4, w1h + n * ENC_DIM + kc + q * 8);
        }
    };

    float4 fr[2];                              // A prefetch regs (8 floats)
    auto ldgA = [&](int c) {
        const float4* src = reinterpret_cast<const float4*>(
            enc + (row0 + ar) * ENC_DIM + c * KC + aq * 8);
        fr[0] = src[0]; fr[1] = src[1];
    };
    auto stsA = [&](int c) {                   // A buffer c is unique: no reuse
        __half2 h0 = __floats2half2_rn(fr[0].x, fr[0].y);
        __half2 h1 = __floats2half2_rn(fr[0].z, fr[0].w);
        __half2 h2 = __floats2half2_rn(fr[1].x, fr[1].y);
        __half2 h3 = __floats2half2_rn(fr[1].z, fr[1].w);
        uint4 w = make_uint4(*reinterpret_cast<uint32_t*>(&h0),
                             *reinterpret_cast<uint32_t*>(&h1),
                             *reinterpret_cast<uint32_t*>(&h2),
                             *reinterpret_cast<uint32_t*>(&h3));
        *reinterpret_cast<uint4*>(sm + c * ASZ + ar * P + aq * 4) = w;
    };

    float d[2][8][4];
#pragma unroll
    for (int h = 0; h < 2; ++h)
#pragma unroll
        for (int j = 0; j < 8; ++j)
#pragma unroll
            for (int q = 0; q < 4; ++q) d[h][j][q] = 0.f;

    // prologue: B0,B1 in flight; A0,A1 staged; regs hold A2
    stageB(0); cp_commit();
    stageB(1); cp_commit();
    ldgA(0); stsA(0);
    ldgA(1); stsA(1);
    ldgA(2);

    for (int c = 0; c < NCHUNK; ++c) {
        if (c < NCHUNK - 1) cp_wait<1>(); else cp_wait<0>();
        __syncthreads();          // B(c) + A(c) visible; B buf (c+2)%3 free

        if (c + 2 < NCHUNK) {
            stsA(c + 2);          // from regs loaded last iter
            stageB(c + 2); cp_commit();
            if (c + 3 < NCHUNK) ldgA(c + 3);
        }

        const unsigned abase = smem_base + (c * ASZ) * 4 + a_lane_off * 4;
        const unsigned bbase = smem_base + (NCHUNK * ASZ + (c % 3) * BSZ) * 4
                               + b_lane_off * 4;

#pragma unroll
        for (int s = 0; s < NKS; ++s) {
            unsigned a[2][4];
            ldsm4(a[0], abase + (s * 8) * 4);
            ldsm4(a[1], abase + (16 * P + s * 8) * 4);
#pragma unroll
            for (int jp = 0; jp < 4; ++jp) {
                unsigned bb[4];
                ldsm4(bb, bbase + (jp * 16 * P + s * 8) * 4);
                mma_f16(d[0][2 * jp],     a[0], bb[0], bb[1]);
                mma_f16(d[1][2 * jp],     a[1], bb[0], bb[1]);
                mma_f16(d[0][2 * jp + 1], a[0], bb[2], bb[3]);
                mma_f16(d[1][2 * jp + 1], a[1], bb[2], bb[3]);
            }
        }
    }

    // Score epilogue: +dec_proj, tanh.approx, *v, warp-reduce, smem combine
    const int g = lane >> 2;
#pragma unroll
    for (int h = 0; h < 2; ++h) {
        float s0 = 0.f, s1 = 0.f;
#pragma unroll
        for (int j = 0; j < 8; ++j) {
            const int n0 = nb + 8 * j + 2 * t;
            const float vv0 = vs[n0],  vv1 = vs[n0 + 1];
            const float dd0 = dps[n0], dd1 = dps[n0 + 1];
            s0 += vv0 * tanha(d[h][j][0] + dd0) + vv1 * tanha(d[h][j][1] + dd1);
            s1 += vv0 * tanha(d[h][j][2] + dd0) + vv1 * tanha(d[h][j][3] + dd1);
        }
        s0 += __shfl_xor_sync(0xffffffffu, s0, 1);
        s0 += __shfl_xor_sync(0xffffffffu, s0, 2);
        s1 += __shfl_xor_sync(0xffffffffu, s1, 1);
        s1 += __shfl_xor_sync(0xffffffffu, s1, 2);
        if (t == 0) {
            atomicAdd(&ssc[m0 + 16 * h + g], s0);
            atomicAdd(&ssc[m0 + 16 * h + 8 + g], s1);
        }
    }
    __syncthreads();
    if (tid < MT) scores[row0 + tid] = ssc[tid];

    // ---- fused partial softmax + partial context (flash-style) ----
    if (tid < MT) {
        float s = ssc[tid];
#pragma unroll
        for (int o = 16; o; o >>= 1) s = fmaxf(s, __shfl_xor_sync(0xffffffffu, s, o));
        if (lane == 0) redm[wid] = s;
    }
    __syncthreads();
    if (tid == 0) mc_sh = fmaxf(redm[0], redm[1]);
    __syncthreads();
    const float m_c = mc_sh;

    if (tid < MT) {
        float p = expf(ssc[tid] - m_c);
        ssc[tid] = p;
        float z = p;
#pragma unroll
        for (int o = 16; o; o >>= 1) z += __shfl_xor_sync(0xffffffffu, z, o);
        if (lane == 0) redz[wid] = z;
    }
    __syncthreads();
    if (tid == 0) {
        pm[bid] = m_c;
        pz[bid] = redz[0] + redz[1];
    }

    // partial context: thread owns column e = tid; reads resident fp16 A
    {
        const int ch   = tid >> 5;             // chunk buffer holding k = e
        const int woff = (tid & 31) >> 1;      // word within row
        const int hh   = tid & 1;
        const unsigned* abuf = sm + ch * ASZ + woff;
        float acc = 0.f;
#pragma unroll 8
        for (int r = 0; r < MT; ++r) {
            unsigned w = abuf[r * P];
            __half2 hx = *reinterpret_cast<__half2*>(&w);
            float x = hh ? __high2float(hx) : __low2float(hx);
            acc = fmaf(ssc[r], x, acc);
        }
        pctx[(long long)bid * ENC_DIM + tid] = acc;
    }
}

// ---------------------------------------------------------------------------
// K2: fused combine + probs. grid = B x 256.
// Combine partials (exact flash rescale) -> context, then write probs.
// ---------------------------------------------------------------------------
__global__ void combine_probs_kernel(const float* __restrict__ pm,
                                     const float* __restrict__ pz,
                                     const float* __restrict__ pctx,
                                     const float* __restrict__ scores,
                                     float* __restrict__ out,
                                     int B, int T, int cpb) {
    __shared__ float mc[MAXCPB], wc[MAXCPB];
    __shared__ float m_sh, z_sh;
    const int b = blockIdx.x;
    const int tid = threadIdx.x;

    if (tid < cpb) mc[tid] = pm[b * cpb + tid];
    __syncthreads();
    if (tid == 0) {
        float m = mc[0];
        for (int c = 1; c < cpb; ++c) m = fmaxf(m, mc[c]);
        m_sh = m;
    }
    __syncthreads();
    const float m = m_sh;
    if (tid < cpb) wc[tid] = expf(mc[tid] - m);
    __syncthreads();
    if (tid == 0) {
        float z = 0.f;
        for (int c = 0; c < cpb; ++c) z += pz[b * cpb + c] * wc[c];
        z_sh = z;
    }
    __syncthreads();
    const float invZ = 1.f / z_sh;

    // context
    float acc = 0.f;
    for (int c = 0; c < cpb; ++c)
        acc = fmaf(pctx[((long long)(b * cpb + c)) * ENC_DIM + tid], wc[c], acc);
    out[b * ENC_DIM + tid] = acc * invZ;

    // probs
    float* probs = out + (long long)B * ENC_DIM;
#pragma unroll 4
    for (int t = tid; t < T; t += 256)
        probs[(long long)b * T + t] = expf(scores[b * T + t] - m) * invZ;
}

// ---------------------------------------------------------------------------
extern "C" void kernel_launch(void* const* d_in, const int* in_sizes, int n_in,
                              void* d_out, int out_size) {
    const float* enc = (const float*)d_in[0];   // [B,T,256]
    const float* dec = (const float*)d_in[1];   // [B,256]
    const float* w1  = (const float*)d_in[2];   // [256,256]
    const float* w2  = (const float*)d_in[3];   // [256,256]
    const float* v   = (const float*)d_in[4];   // [1,256]
    float* out = (float*)d_out;

    const int B = in_sizes[1] / ENC_DIM;                 // 64
    const int T = in_sizes[0] / (B * ENC_DIM);           // 2048
    const int cpb = T / MT;                              // 32

    float*  dp_ptr;     cudaGetSymbolAddress((void**)&dp_ptr, g_dp);
    float*  scores_ptr; cudaGetSymbolAddress((void**)&scores_ptr, g_scores);
    __half* w1h_ptr;    cudaGetSymbolAddress((void**)&w1h_ptr, g_w1h);
    float*  pm_ptr;     cudaGetSymbolAddress((void**)&pm_ptr, g_pm);
    float*  pz_ptr;     cudaGetSymbolAddress((void**)&pz_ptr, g_pz);
    float*  pctx_ptr;   cudaGetSymbolAddress((void**)&pctx_ptr, g_pctx);

    cudaFuncSetAttribute(scores_mma_kernel,
                         cudaFuncAttributeMaxDynamicSharedMemorySize, DYN_BYTES);

    prep_kernel<<<128, 256>>>(dec, w2, w1, w1h_ptr, dp_ptr);
    scores_mma_kernel<<<(B * T) / MT, NTHR, DYN_BYTES>>>(
        enc, w1h_ptr, dp_ptr, v, scores_ptr, pm_ptr, pz_ptr, pctx_ptr, T);
    combine_probs_kernel<<<B, 256>>>(pm_ptr, pz_ptr, pctx_ptr, scores_ptr,
                                     out, B, T, cpb);
}

// round 17
// speedup vs baseline: 1.3262x; 1.1590x over previous
#include <cuda_runtime.h>
#include <cuda_fp16.h>
#include <cuda_bf16.h>
#include <math_constants.h>
#include <cstdint>

#define ENC_DIM 256
#define INT_DIM 256
#define MT 64                   // rows per CTA (M)
#define NT 256                  // hidden per CTA (N)
#define KC 32                   // k per chunk
#define NCHUNK (ENC_DIM / KC)   // 8
#define NKS (KC / 16)           // 2 k16 steps per chunk
#define P 20                    // smem pitch in u32 words (16 used + 4 pad)
#define ASZ (MT * P)            // 1280 words (one A chunk buffer)
#define BSZ (NT * P)            // 5120 words (one B stage)
#define BSTG 3                  // B pipeline stages
#define DYN_BYTES ((NCHUNK * ASZ + BSTG * BSZ) * 4)   // 102400 -> 2 CTAs/SM
#define NTHR 256
#define MAXCPB 32               // chunks per batch (T/MT)

// Scratch (allocation-free rule: __device__ globals)
__device__ float  g_dp[64 * INT_DIM];          // dec_proj [B, I]
__device__ float  g_scores[64 * 2048];         // scores   [B, T]
__device__ __half g_w1h[INT_DIM * ENC_DIM];    // w1 as fp16, [n][k]
__device__ float  g_pm[2048];                  // per-CTA local max
__device__ float  g_pz[2048];                  // per-CTA local exp-sum
__device__ float  g_pctx[2048 * ENC_DIM];      // per-CTA partial context

// ---------------------------------------------------------------------------
// helpers
// ---------------------------------------------------------------------------
__device__ __forceinline__ float tanha(float x) {
    float y;
    asm("tanh.approx.f32 %0, %1;" : "=f"(y) : "f"(x));
    return y;
}
__device__ __forceinline__ void cp16(unsigned dst_s, const void* src) {
    asm volatile("cp.async.cg.shared.global [%0], [%1], 16;"
                 :: "r"(dst_s), "l"(src) : "memory");
}
__device__ __forceinline__ void cp_commit() {
    asm volatile("cp.async.commit_group;" ::: "memory");
}
template <int N>
__device__ __forceinline__ void cp_wait() {
    asm volatile("cp.async.wait_group %0;" :: "n"(N) : "memory");
}
__device__ __forceinline__ unsigned s2u(const void* p) {
    return (unsigned)__cvta_generic_to_shared(p);
}
__device__ __forceinline__ void ldsm4(unsigned r[4], unsigned addr) {
    asm volatile("ldmatrix.sync.aligned.m8n8.x4.shared.b16 "
                 "{%0,%1,%2,%3}, [%4];"
                 : "=r"(r[0]), "=r"(r[1]), "=r"(r[2]), "=r"(r[3])
                 : "r"(addr));
}
__device__ __forceinline__ void mma_f16(float d[4], const unsigned a[4],
                                        unsigned b0, unsigned b1) {
    asm volatile(
        "mma.sync.aligned.m16n8k16.row.col.f32.f16.f16.f32 "
        "{%0,%1,%2,%3}, {%4,%5,%6,%7}, {%8,%9}, {%0,%1,%2,%3};"
        : "+f"(d[0]), "+f"(d[1]), "+f"(d[2]), "+f"(d[3])
        : "r"(a[0]), "r"(a[1]), "r"(a[2]), "r"(a[3]), "r"(b0), "r"(b1));
}

// ---------------------------------------------------------------------------
// K0: prep. grid = 576 x 256.
//  blocks [0,512):   decproj. bid -> (b = bid>>3, ig = bid&7). Block computes
//                    dp[b, ig*32 .. ig*32+32): warp w owns 4 outputs, each
//                    reduced by the full warp (coalesced k, 32 LDGs in flight).
//  blocks [512,576): w1 -> fp16 slice (1024 elements per block)
// ---------------------------------------------------------------------------
__global__ void prep_kernel(const float* __restrict__ dec,
                            const float* __restrict__ w2,
                            const float* __restrict__ w1,
                            __half* __restrict__ w1h,
                            float* __restrict__ dp) {
    const int tid = threadIdx.x;

    if (blockIdx.x >= 512) {                   // w1 -> fp16 conversion
        const int base = (blockIdx.x - 512) * 1024 + tid * 4;
        float4 wv = *reinterpret_cast<const float4*>(w1 + base);
        __half2 p0 = __floats2half2_rn(wv.x, wv.y);
        __half2 p1 = __floats2half2_rn(wv.z, wv.w);
        uint2 pk = make_uint2(*reinterpret_cast<uint32_t*>(&p0),
                              *reinterpret_cast<uint32_t*>(&p1));
        *reinterpret_cast<uint2*>(w1h + base) = pk;
        return;
    }

    __shared__ float ds[ENC_DIM];
    const int b  = blockIdx.x >> 3;
    const int ig = blockIdx.x & 7;
    const int lane = tid & 31, wid = tid >> 5;

    ds[tid] = dec[b * ENC_DIM + tid];
    __syncthreads();

    // warp wid: outputs i = ig*32 + wid*4 + {0..3}
    const int ibase = ig * 32 + wid * 4;
    float acc[4];
#pragma unroll
    for (int o = 0; o < 4; ++o) {
        const int i = ibase + o;
        float a = 0.f;
#pragma unroll
        for (int kk = 0; kk < 8; ++kk) {
            const int k = kk * 32 + lane;
            a = fmaf(__ldg(w2 + i * ENC_DIM + k), ds[k], a);
        }
        acc[o] = a;
    }
#pragma unroll
    for (int o = 0; o < 4; ++o) {
#pragma unroll
        for (int s = 16; s; s >>= 1)
            acc[o] += __shfl_xor_sync(0xffffffffu, acc[o], s);
        if (lane == 0) dp[b * INT_DIM + ibase + o] = acc[o];
    }
}

// ---------------------------------------------------------------------------
// K1: scores + fused partial-softmax/partial-context (round-12 mainloop).
// CTA = 64 rows x 256 n, 256 thr, 2 CTAs/SM. A resident (8 chunk buffers),
// B 3-stage cp.async pipeline.
// ---------------------------------------------------------------------------
__global__ void __launch_bounds__(NTHR, 2)
scores_mma_kernel(const float* __restrict__ enc,
                  const __half* __restrict__ w1h,
                  const float* __restrict__ dp,
                  const float* __restrict__ v,
                  float* __restrict__ scores,
                  float* __restrict__ pm,
                  float* __restrict__ pz,
                  float* __restrict__ pctx,
                  int T) {
    extern __shared__ unsigned sm[];          // A0..A7 | B0..B2
    __shared__ float dps[INT_DIM], vs[INT_DIM], ssc[MT];
    __shared__ float redm[2], redz[2], mc_sh;

    const int tid  = threadIdx.x;
    const int wid  = tid >> 5;
    const int lane = tid & 31;
    const int t    = lane & 3;
    const int m0   = (wid & 1) * 32;
    const int nb   = (wid >> 1) * 64;
    const int bid  = blockIdx.x;
    const long long row0 = (long long)bid * MT;
    const int b = (int)(row0 / T);

    dps[tid] = dp[b * INT_DIM + tid];
    vs[tid]  = __ldg(v + tid);
    if (tid < MT) ssc[tid] = 0.f;

    const unsigned smem_base = s2u(sm);

    const unsigned a_lane_off = (unsigned)((m0 + (lane & 15)) * P + ((lane >> 4) << 2));
    const unsigned b_lane_off = (unsigned)((nb + ((lane >> 4) & 1) * 8 + (lane & 7)) * P
                                           + ((lane >> 3) & 1) * 4);

    const int ar = tid >> 2;                  // A staging: row (0..63)
    const int aq = tid & 3;                   // A staging: 16B quarter of row

    auto stageB = [&](int c) {
        const int kc = c * KC;
        const unsigned bb = smem_base + (NCHUNK * ASZ + (c % 3) * BSZ) * 4;
#pragma unroll
        for (int i = tid; i < NT * 4; i += NTHR) {
            int n = i >> 2, q = i & 3;
            cp16(bb + (n * P + q * 4) * 4, w1h + n * ENC_DIM + kc + q * 8);
        }
    };

    float4 fr[2];                              // A prefetch regs (8 floats)
    auto ldgA = [&](int c) {
        const float4* src = reinterpret_cast<const float4*>(
            enc + (row0 + ar) * ENC_DIM + c * KC + aq * 8);
        fr[0] = src[0]; fr[1] = src[1];
    };
    auto stsA = [&](int c) {                   // A buffer c is unique: no reuse
        __half2 h0 = __floats2half2_rn(fr[0].x, fr[0].y);
        __half2 h1 = __floats2half2_rn(fr[0].z, fr[0].w);
        __half2 h2 = __floats2half2_rn(fr[1].x, fr[1].y);
        __half2 h3 = __floats2half2_rn(fr[1].z, fr[1].w);
        uint4 w = make_uint4(*reinterpret_cast<uint32_t*>(&h0),
                             *reinterpret_cast<uint32_t*>(&h1),
                             *reinterpret_cast<uint32_t*>(&h2),
                             *reinterpret_cast<uint32_t*>(&h3));
        *reinterpret_cast<uint4*>(sm + c * ASZ + ar * P + aq * 4) = w;
    };

    float d[2][8][4];
#pragma unroll
    for (int h = 0; h < 2; ++h)
#pragma unroll
        for (int j = 0; j < 8; ++j)
#pragma unroll
            for (int q = 0; q < 4; ++q) d[h][j][q] = 0.f;

    // prologue: B0,B1 in flight; A0,A1 staged; regs hold A2
    stageB(0); cp_commit();
    stageB(1); cp_commit();
    ldgA(0); stsA(0);
    ldgA(1); stsA(1);
    ldgA(2);

    for (int c = 0; c < NCHUNK; ++c) {
        if (c < NCHUNK - 1) cp_wait<1>(); else cp_wait<0>();
        __syncthreads();          // B(c) + A(c) visible; B buf (c+2)%3 free

        if (c + 2 < NCHUNK) {
            stsA(c + 2);          // from regs loaded last iter
            stageB(c + 2); cp_commit();
            if (c + 3 < NCHUNK) ldgA(c + 3);
        }

        const unsigned abase = smem_base + (c * ASZ) * 4 + a_lane_off * 4;
        const unsigned bbase = smem_base + (NCHUNK * ASZ + (c % 3) * BSZ) * 4
                               + b_lane_off * 4;

#pragma unroll
        for (int s = 0; s < NKS; ++s) {
            unsigned a[2][4];
            ldsm4(a[0], abase + (s * 8) * 4);
            ldsm4(a[1], abase + (16 * P + s * 8) * 4);
#pragma unroll
            for (int jp = 0; jp < 4; ++jp) {
                unsigned bb[4];
                ldsm4(bb, bbase + (jp * 16 * P + s * 8) * 4);
                mma_f16(d[0][2 * jp],     a[0], bb[0], bb[1]);
                mma_f16(d[1][2 * jp],     a[1], bb[0], bb[1]);
                mma_f16(d[0][2 * jp + 1], a[0], bb[2], bb[3]);
                mma_f16(d[1][2 * jp + 1], a[1], bb[2], bb[3]);
            }
        }
    }

    // Score epilogue: +dec_proj, tanh.approx, *v, warp-reduce, smem combine
    const int g = lane >> 2;
#pragma unroll
    for (int h = 0; h < 2; ++h) {
        float s0 = 0.f, s1 = 0.f;
#pragma unroll
        for (int j = 0; j < 8; ++j) {
            const int n0 = nb + 8 * j + 2 * t;
            const float vv0 = vs[n0],  vv1 = vs[n0 + 1];
            const float dd0 = dps[n0], dd1 = dps[n0 + 1];
            s0 += vv0 * tanha(d[h][j][0] + dd0) + vv1 * tanha(d[h][j][1] + dd1);
            s1 += vv0 * tanha(d[h][j][2] + dd0) + vv1 * tanha(d[h][j][3] + dd1);
        }
        s0 += __shfl_xor_sync(0xffffffffu, s0, 1);
        s0 += __shfl_xor_sync(0xffffffffu, s0, 2);
        s1 += __shfl_xor_sync(0xffffffffu, s1, 1);
        s1 += __shfl_xor_sync(0xffffffffu, s1, 2);
        if (t == 0) {
            atomicAdd(&ssc[m0 + 16 * h + g], s0);
            atomicAdd(&ssc[m0 + 16 * h + 8 + g], s1);
        }
    }
    __syncthreads();
    if (tid < MT) scores[row0 + tid] = ssc[tid];

    // ---- fused partial softmax + partial context (flash-style) ----
    if (tid < MT) {
        float s = ssc[tid];
#pragma unroll
        for (int o = 16; o; o >>= 1) s = fmaxf(s, __shfl_xor_sync(0xffffffffu, s, o));
        if (lane == 0) redm[wid] = s;
    }
    __syncthreads();
    if (tid == 0) mc_sh = fmaxf(redm[0], redm[1]);
    __syncthreads();
    const float m_c = mc_sh;

    if (tid < MT) {
        float p = expf(ssc[tid] - m_c);
        ssc[tid] = p;
        float z = p;
#pragma unroll
        for (int o = 16; o; o >>= 1) z += __shfl_xor_sync(0xffffffffu, z, o);
        if (lane == 0) redz[wid] = z;
    }
    __syncthreads();
    if (tid == 0) {
        pm[bid] = m_c;
        pz[bid] = redz[0] + redz[1];
    }

    // partial context: thread owns column e = tid; reads resident fp16 A
    {
        const int ch   = tid >> 5;             // chunk buffer holding k = e
        const int woff = (tid & 31) >> 1;      // word within row
        const int hh   = tid & 1;
        const unsigned* abuf = sm + ch * ASZ + woff;
        float acc = 0.f;
#pragma unroll 8
        for (int r = 0; r < MT; ++r) {
            unsigned w = abuf[r * P];
            __half2 hx = *reinterpret_cast<__half2*>(&w);
            float x = hh ? __high2float(hx) : __low2float(hx);
            acc = fmaf(ssc[r], x, acc);
        }
        pctx[(long long)bid * ENC_DIM + tid] = acc;
    }
}

// ---------------------------------------------------------------------------
// K2: fused combine + probs. grid = B x 256.
// ---------------------------------------------------------------------------
__global__ void combine_probs_kernel(const float* __restrict__ pm,
                                     const float* __restrict__ pz,
                                     const float* __restrict__ pctx,
                                     const float* __restrict__ scores,
                                     float* __restrict__ out,
                                     int B, int T, int cpb) {
    __shared__ float mc[MAXCPB], wc[MAXCPB];
    __shared__ float m_sh, z_sh;
    const int b = blockIdx.x;
    const int tid = threadIdx.x;

    if (tid < cpb) mc[tid] = pm[b * cpb + tid];
    __syncthreads();
    if (tid == 0) {
        float m = mc[0];
        for (int c = 1; c < cpb; ++c) m = fmaxf(m, mc[c]);
        m_sh = m;
    }
    __syncthreads();
    const float m = m_sh;
    if (tid < cpb) wc[tid] = expf(mc[tid] - m);
    __syncthreads();
    if (tid == 0) {
        float z = 0.f;
        for (int c = 0; c < cpb; ++c) z += pz[b * cpb + c] * wc[c];
        z_sh = z;
    }
    __syncthreads();
    const float invZ = 1.f / z_sh;

    // context
    float acc = 0.f;
    for (int c = 0; c < cpb; ++c)
        acc = fmaf(pctx[((long long)(b * cpb + c)) * ENC_DIM + tid], wc[c], acc);
    out[b * ENC_DIM + tid] = acc * invZ;

    // probs
    float* probs = out + (long long)B * ENC_DIM;
#pragma unroll 4
    for (int t = tid; t < T; t += 256)
        probs[(long long)b * T + t] = expf(scores[b * T + t] - m) * invZ;
}

// ---------------------------------------------------------------------------
extern "C" void kernel_launch(void* const* d_in, const int* in_sizes, int n_in,
                              void* d_out, int out_size) {
    const float* enc = (const float*)d_in[0];   // [B,T,256]
    const float* dec = (const float*)d_in[1];   // [B,256]
    const float* w1  = (const float*)d_in[2];   // [256,256]
    const float* w2  = (const float*)d_in[3];   // [256,256]
    const float* v   = (const float*)d_in[4];   // [1,256]
    float* out = (float*)d_out;

    const int B = in_sizes[1] / ENC_DIM;                 // 64
    const int T = in_sizes[0] / (B * ENC_DIM);           // 2048
    const int cpb = T / MT;                              // 32

    float*  dp_ptr;     cudaGetSymbolAddress((void**)&dp_ptr, g_dp);
    float*  scores_ptr; cudaGetSymbolAddress((void**)&scores_ptr, g_scores);
    __half* w1h_ptr;    cudaGetSymbolAddress((void**)&w1h_ptr, g_w1h);
    float*  pm_ptr;     cudaGetSymbolAddress((void**)&pm_ptr, g_pm);
    float*  pz_ptr;     cudaGetSymbolAddress((void**)&pz_ptr, g_pz);
    float*  pctx_ptr;   cudaGetSymbolAddress((void**)&pctx_ptr, g_pctx);

    cudaFuncSetAttribute(scores_mma_kernel,
                         cudaFuncAttributeMaxDynamicSharedMemorySize, DYN_BYTES);

    prep_kernel<<<576, 256>>>(dec, w2, w1, w1h_ptr, dp_ptr);
    scores_mma_kernel<<<(B * T) / MT, NTHR, DYN_BYTES>>>(
        enc, w1h_ptr, dp_ptr, v, scores_ptr, pm_ptr, pz_ptr, pctx_ptr, T);
    combine_probs_kernel<<<B, 256>>>(pm_ptr, pz_ptr, pctx_ptr, scores_ptr,
                                     out, B, T, cpb);
}